// round 3
// baseline (speedup 1.0000x reference)
#include <cuda_runtime.h>
#include <cstdint>

// Problem constants (fixed shapes for this problem)
#define EMBED 64
#define MAX_NODES 100032   // headroom over 100000

// Scratch: h = relu(x W^T + b)  [N, 64], and per-node counts
__device__ float g_h[MAX_NODES * EMBED];
__device__ float g_cnt[MAX_NODES];

// ---------------------------------------------------------------------------
// Kernel 0: zero out (d_out) and counts.  d_out poisoned to 0xAA each replay.
// ---------------------------------------------------------------------------
__global__ void zero_kernel(float4* __restrict__ out4, int n4, int n_nodes) {
    int i = blockIdx.x * blockDim.x + threadIdx.x;
    if (i < n4) out4[i] = make_float4(0.f, 0.f, 0.f, 0.f);
    if (i < n_nodes) g_cnt[i] = 0.f;
}

// ---------------------------------------------------------------------------
// Kernel 1: h = relu(x @ W^T + b)
// x: [N,64], W: [64,64] (out,in), b: [64]
// One thread per row. x row in registers (16 float4), W broadcast from smem.
// ---------------------------------------------------------------------------
__global__ void __launch_bounds__(256) linear_relu_kernel(
    const float* __restrict__ x, const float* __restrict__ W,
    const float* __restrict__ b, int N)
{
    __shared__ float4 sW[EMBED * 16];   // W[o][d] as float4 chunks
    __shared__ float  sb[EMBED];

    int tid = threadIdx.x;
    const float4* W4 = reinterpret_cast<const float4*>(W);
    for (int i = tid; i < EMBED * 16; i += 256) sW[i] = W4[i];
    if (tid < EMBED) sb[tid] = b[tid];
    __syncthreads();

    int row = blockIdx.x * 256 + tid;
    if (row >= N) return;

    float4 xr[16];
    const float4* xp = reinterpret_cast<const float4*>(x + (size_t)row * EMBED);
    #pragma unroll
    for (int i = 0; i < 16; i++) xr[i] = __ldg(xp + i);

    float4* outp = reinterpret_cast<float4*>(g_h + (size_t)row * EMBED);
    #pragma unroll 4
    for (int o4 = 0; o4 < 16; o4++) {
        float4 res;
        float* rp = &res.x;
        #pragma unroll
        for (int j = 0; j < 4; j++) {
            int o = o4 * 4 + j;
            float acc = sb[o];
            #pragma unroll
            for (int d4 = 0; d4 < 16; d4++) {
                float4 w = sW[o * 16 + d4];
                acc = fmaf(xr[d4].x, w.x, acc);
                acc = fmaf(xr[d4].y, w.y, acc);
                acc = fmaf(xr[d4].z, w.z, acc);
                acc = fmaf(xr[d4].w, w.w, acc);
            }
            rp[j] = fmaxf(acc, 0.f);
        }
        outp[o4] = res;
    }
}

// ---------------------------------------------------------------------------
// Kernel 2: per-edge scatter.  16 threads per edge, float4 per thread.
// out[src] += h[tgt];  cnt[src] += 1
// Uses non-returning vector atomics (red.global.add.v4.f32, sm_90+).
// edge indices are INT32 (jax default: x64 disabled).
// ---------------------------------------------------------------------------
__global__ void __launch_bounds__(256) scatter_kernel(
    const int* __restrict__ edge_src,   // edge_index[0]
    const int* __restrict__ edge_tgt,   // edge_index[1]
    float* __restrict__ out, int E, int N)
{
    int e = blockIdx.x * 16 + (threadIdx.x >> 4);   // 16 edges / block
    int c = threadIdx.x & 15;                        // float4 chunk 0..15
    if (e >= E) return;

    int src = __ldg(edge_src + e);
    int tgt = __ldg(edge_tgt + e);
    if ((unsigned)src >= (unsigned)N || (unsigned)tgt >= (unsigned)N) return;

    float4 v = __ldg(reinterpret_cast<const float4*>(g_h + (size_t)tgt * EMBED) + c);

    float* dst = out + (size_t)src * EMBED + c * 4;
    asm volatile("red.global.add.v4.f32 [%0], {%1,%2,%3,%4};"
                 :: "l"(dst), "f"(v.x), "f"(v.y), "f"(v.z), "f"(v.w)
                 : "memory");

    if (c == 0) {
        float one = 1.0f;
        asm volatile("red.global.add.f32 [%0], %1;"
                     :: "l"(g_cnt + src), "f"(one) : "memory");
    }
}

// ---------------------------------------------------------------------------
// Kernel 3: mean normalization: out[i][:] *= 1 / max(cnt[i], 1)
// ---------------------------------------------------------------------------
__global__ void __launch_bounds__(256) normalize_kernel(float4* __restrict__ out4, int n4)
{
    int i = blockIdx.x * blockDim.x + threadIdx.x;
    if (i >= n4) return;
    int row = i >> 4;                 // 16 float4 per row
    float cnt = g_cnt[row];
    float inv = (cnt > 1.0f) ? __frcp_rn(cnt) : 1.0f;
    float4 v = out4[i];
    v.x *= inv; v.y *= inv; v.z *= inv; v.w *= inv;
    out4[i] = v;
}

// ---------------------------------------------------------------------------
// Launch.  Inputs (metadata order): x [N*64] f32, edge_index [2*E] int32,
// W [64*64] f32, b [64] f32, num_node scalar.
// ---------------------------------------------------------------------------
extern "C" void kernel_launch(void* const* d_in, const int* in_sizes, int n_in,
                              void* d_out, int out_size)
{
    const float* x = (const float*)d_in[0];
    const int* edge = (const int*)d_in[1];
    const float* W = (const float*)d_in[2];
    const float* b = (const float*)d_in[3];

    int N = in_sizes[0] / EMBED;      // 100000
    int E = in_sizes[1] / 2;          // 1600000
    float* out = (float*)d_out;

    int n4 = N * (EMBED / 4);         // float4 count of output

    zero_kernel<<<(n4 + 255) / 256, 256>>>((float4*)out, n4, N);
    linear_relu_kernel<<<(N + 255) / 256, 256>>>(x, W, b, N);
    scatter_kernel<<<(E + 15) / 16, 256>>>(edge, edge + E, out, E, N);
    normalize_kernel<<<(n4 + 255) / 256, 256>>>((float4*)out, n4);
}

// round 4
// speedup vs baseline: 1.3074x; 1.3074x over previous
#include <cuda_runtime.h>
#include <cstdint>

#define EMBED 64
#define MAX_NODES 100032
#define MAX_EDGES 1600000
#define SCAN_BLK 1024

// Scratch
__device__ float g_h[(size_t)MAX_NODES * EMBED];   // relu(x W^T + b)
__device__ int   g_hist[MAX_NODES];                // degree per src node
__device__ int   g_off[MAX_NODES];                 // exclusive prefix (CSR row ptr)
__device__ int   g_cursor[MAX_NODES];              // running cursor for bucket fill
__device__ int   g_blocksum[256];
__device__ int   g_sorted_tgt[MAX_EDGES];          // tgt ids grouped by src

// ---------------------------------------------------------------------------
// 0: zero histogram
// ---------------------------------------------------------------------------
__global__ void zero_hist_kernel(int n) {
    int i = blockIdx.x * blockDim.x + threadIdx.x;
    if (i < n) g_hist[i] = 0;
}

// ---------------------------------------------------------------------------
// 1: degree histogram over src
// ---------------------------------------------------------------------------
__global__ void hist_kernel(const int* __restrict__ src, int E, int N) {
    int e = blockIdx.x * blockDim.x + threadIdx.x;
    if (e >= E) return;
    int s = __ldg(src + e);
    if ((unsigned)s < (unsigned)N) atomicAdd(&g_hist[s], 1);
}

// ---------------------------------------------------------------------------
// 2a: per-block inclusive scan (Hillis-Steele), exclusive result + block sums
// ---------------------------------------------------------------------------
__global__ void scan1_kernel(int n) {
    __shared__ int s[SCAN_BLK];
    int tid = threadIdx.x;
    int i = blockIdx.x * SCAN_BLK + tid;
    int v = (i < n) ? g_hist[i] : 0;
    s[tid] = v;
    __syncthreads();
    #pragma unroll
    for (int d = 1; d < SCAN_BLK; d <<= 1) {
        int t = (tid >= d) ? s[tid - d] : 0;
        __syncthreads();
        s[tid] += t;
        __syncthreads();
    }
    if (i < n) g_off[i] = s[tid] - v;            // exclusive within block
    if (tid == SCAN_BLK - 1) g_blocksum[blockIdx.x] = s[tid];
}

// 2b: scan the block sums (single block)
__global__ void scan2_kernel(int nb) {
    __shared__ int s[256];
    int tid = threadIdx.x;
    int v = (tid < nb) ? g_blocksum[tid] : 0;
    s[tid] = v;
    __syncthreads();
    #pragma unroll
    for (int d = 1; d < 256; d <<= 1) {
        int t = (tid >= d) ? s[tid - d] : 0;
        __syncthreads();
        s[tid] += t;
        __syncthreads();
    }
    if (tid < nb) g_blocksum[tid] = s[tid] - v;  // exclusive
}

// 2c: add block offsets, init cursors
__global__ void scan3_kernel(int n) {
    int i = blockIdx.x * blockDim.x + threadIdx.x;
    if (i >= n) return;
    int off = g_off[i] + g_blocksum[i / SCAN_BLK];
    g_off[i] = off;
    g_cursor[i] = off;
}

// ---------------------------------------------------------------------------
// 3: bucket-fill tgt ids grouped by src
// ---------------------------------------------------------------------------
__global__ void fill_kernel(const int* __restrict__ src,
                            const int* __restrict__ tgt, int E, int N) {
    int e = blockIdx.x * blockDim.x + threadIdx.x;
    if (e >= E) return;
    int s = __ldg(src + e);
    int t = __ldg(tgt + e);
    if ((unsigned)s >= (unsigned)N || (unsigned)t >= (unsigned)N) return;
    int pos = atomicAdd(&g_cursor[s], 1);
    g_sorted_tgt[pos] = t;
}

// ---------------------------------------------------------------------------
// 4: h = relu(x @ W^T + b). One thread per row.
// ---------------------------------------------------------------------------
__global__ void __launch_bounds__(256) linear_relu_kernel(
    const float* __restrict__ x, const float* __restrict__ W,
    const float* __restrict__ b, int N)
{
    __shared__ float4 sW[EMBED * 16];
    __shared__ float  sb[EMBED];
    int tid = threadIdx.x;
    const float4* W4 = reinterpret_cast<const float4*>(W);
    for (int i = tid; i < EMBED * 16; i += 256) sW[i] = W4[i];
    if (tid < EMBED) sb[tid] = b[tid];
    __syncthreads();

    int row = blockIdx.x * 256 + tid;
    if (row >= N) return;

    float4 xr[16];
    const float4* xp = reinterpret_cast<const float4*>(x + (size_t)row * EMBED);
    #pragma unroll
    for (int i = 0; i < 16; i++) xr[i] = __ldg(xp + i);

    float4* outp = reinterpret_cast<float4*>(g_h + (size_t)row * EMBED);
    #pragma unroll 4
    for (int o4 = 0; o4 < 16; o4++) {
        float4 res;
        float* rp = &res.x;
        #pragma unroll
        for (int j = 0; j < 4; j++) {
            int o = o4 * 4 + j;
            float acc = sb[o];
            #pragma unroll
            for (int d4 = 0; d4 < 16; d4++) {
                float4 w = sW[o * 16 + d4];
                acc = fmaf(xr[d4].x, w.x, acc);
                acc = fmaf(xr[d4].y, w.y, acc);
                acc = fmaf(xr[d4].z, w.z, acc);
                acc = fmaf(xr[d4].w, w.w, acc);
            }
            rp[j] = fmaxf(acc, 0.f);
        }
        outp[o4] = res;
    }
}

// ---------------------------------------------------------------------------
// 5: aggregate. One warp per node; lane owns 2 channels (float2).
//    out[node] = (1/max(deg,1)) * sum_{i in bucket} h[tgt_i]
// ---------------------------------------------------------------------------
__global__ void __launch_bounds__(256) aggregate_kernel(float* __restrict__ out, int N)
{
    int warp = threadIdx.x >> 5;
    int lane = threadIdx.x & 31;
    int node = blockIdx.x * 8 + warp;
    if (node >= N) return;

    int beg = g_off[node];
    int deg = g_hist[node];
    int end = beg + deg;

    float2 a0 = {0.f, 0.f}, a1 = {0.f, 0.f}, a2 = {0.f, 0.f}, a3 = {0.f, 0.f};
    int i = beg;
    for (; i + 4 <= end; i += 4) {
        int t0 = __ldg(g_sorted_tgt + i);
        int t1 = __ldg(g_sorted_tgt + i + 1);
        int t2 = __ldg(g_sorted_tgt + i + 2);
        int t3 = __ldg(g_sorted_tgt + i + 3);
        float2 v0 = __ldg(reinterpret_cast<const float2*>(g_h + (size_t)t0 * EMBED) + lane);
        float2 v1 = __ldg(reinterpret_cast<const float2*>(g_h + (size_t)t1 * EMBED) + lane);
        float2 v2 = __ldg(reinterpret_cast<const float2*>(g_h + (size_t)t2 * EMBED) + lane);
        float2 v3 = __ldg(reinterpret_cast<const float2*>(g_h + (size_t)t3 * EMBED) + lane);
        a0.x += v0.x; a0.y += v0.y;
        a1.x += v1.x; a1.y += v1.y;
        a2.x += v2.x; a2.y += v2.y;
        a3.x += v3.x; a3.y += v3.y;
    }
    for (; i < end; i++) {
        int t = __ldg(g_sorted_tgt + i);
        float2 v = __ldg(reinterpret_cast<const float2*>(g_h + (size_t)t * EMBED) + lane);
        a0.x += v.x; a0.y += v.y;
    }
    float sx = (a0.x + a1.x) + (a2.x + a3.x);
    float sy = (a0.y + a1.y) + (a2.y + a3.y);
    float inv = (deg > 1) ? __frcp_rn((float)deg) : 1.0f;
    float2 r; r.x = sx * inv; r.y = sy * inv;
    reinterpret_cast<float2*>(out + (size_t)node * EMBED)[lane] = r;
}

// ---------------------------------------------------------------------------
// Launch.  Inputs: x [N*64] f32, edge_index [2*E] int32, W [64*64] f32,
// b [64] f32, num_node scalar.
// ---------------------------------------------------------------------------
extern "C" void kernel_launch(void* const* d_in, const int* in_sizes, int n_in,
                              void* d_out, int out_size)
{
    const float* x = (const float*)d_in[0];
    const int* edge = (const int*)d_in[1];
    const float* W = (const float*)d_in[2];
    const float* b = (const float*)d_in[3];

    int N = in_sizes[0] / EMBED;      // 100000
    int E = in_sizes[1] / 2;          // 1600000
    float* out = (float*)d_out;

    const int* src = edge;
    const int* tgt = edge + E;

    int nScanBlocks = (N + SCAN_BLK - 1) / SCAN_BLK;   // 98

    zero_hist_kernel<<<(N + 255) / 256, 256>>>(N);
    hist_kernel<<<(E + 255) / 256, 256>>>(src, E, N);
    scan1_kernel<<<nScanBlocks, SCAN_BLK>>>(N);
    scan2_kernel<<<1, 256>>>(nScanBlocks);
    scan3_kernel<<<(N + 255) / 256, 256>>>(N);
    fill_kernel<<<(E + 255) / 256, 256>>>(src, tgt, E, N);
    linear_relu_kernel<<<(N + 255) / 256, 256>>>(x, W, b, N);
    aggregate_kernel<<<(N + 7) / 8, 256>>>(out, N);
}